// round 15
// baseline (speedup 1.0000x reference)
#include <cuda_runtime.h>
#include <cuda_bf16.h>
#include <math.h>
#include <cstdint>

// ---------------------------------------------------------------------------
// Problem constants
// ---------------------------------------------------------------------------
#define B_    16
#define N1_   4096
#define N2_   1024
#define KNB   32
#define CIN0  67
#define CPAD  72              // padded to 288B rows (9 aligned 32B sectors)
#define C0    64
#define C1O   64
#define C2    128
#define M_    (B_ * N2_ * KNB)     // 524288
#define NB0T  (M_ / 256)           // 2048
#define NB1T  (M_ / 256)           // 2048
#define NB2T  (M_ / 128)           // 4096
#define CNT_  524288.0f
#define EPS_  1e-5f

// ---------------------------------------------------------------------------
// mma.sync / ldmatrix helpers (baseline PTX, works on compute_103)
// ---------------------------------------------------------------------------
__device__ __forceinline__ void mma_bf16(float* d, const uint32_t* a, const uint32_t* b) {
    asm volatile(
        "mma.sync.aligned.m16n8k16.row.col.f32.bf16.bf16.f32 "
        "{%0,%1,%2,%3}, {%4,%5,%6,%7}, {%8,%9}, {%0,%1,%2,%3};"
        : "+f"(d[0]), "+f"(d[1]), "+f"(d[2]), "+f"(d[3])
        : "r"(a[0]), "r"(a[1]), "r"(a[2]), "r"(a[3]), "r"(b[0]), "r"(b[1]));
}
__device__ __forceinline__ void ldsm_x4(uint32_t* r, uint32_t addr) {
    asm volatile("ldmatrix.sync.aligned.m8n8.x4.shared.b16 {%0,%1,%2,%3}, [%4];"
        : "=r"(r[0]), "=r"(r[1]), "=r"(r[2]), "=r"(r[3]) : "r"(addr));
}
// swizzled smem address for bf16 tiles with 128-byte rows (64 bf16/row)
__device__ __forceinline__ uint32_t sw_off(uint32_t base32, int row, int col) {
    uint32_t byte = (uint32_t)(row * 128 + col * 2);
    byte ^= (byte >> 3) & 0x70;
    return base32 + byte;
}
#define SMEM_SWIZZLE_128B(b) ((b) ^ (((b) >> 3) & 0x70))

// bf16 hi/lo split of two fp32 values, packed as bf16x2 words
__device__ __forceinline__ void split2(float a, float b, uint32_t& hi, uint32_t& lo) {
    __nv_bfloat16 ha = __float2bfloat16(a), hb = __float2bfloat16(b);
    __nv_bfloat16 la = __float2bfloat16(a - __bfloat162float(ha));
    __nv_bfloat16 lb = __float2bfloat16(b - __bfloat162float(hb));
    hi = (uint32_t)__bfloat16_as_ushort(ha) | ((uint32_t)__bfloat16_as_ushort(hb) << 16);
    lo = (uint32_t)__bfloat16_as_ushort(la) | ((uint32_t)__bfloat16_as_ushort(lb) << 16);
}

// butterfly reductions over the g-lanes (lane bits 2..4)
__device__ __forceinline__ float redg_sum(float v) {
    v += __shfl_xor_sync(0xffffffffu, v, 4);
    v += __shfl_xor_sync(0xffffffffu, v, 8);
    v += __shfl_xor_sync(0xffffffffu, v, 16);
    return v;
}
__device__ __forceinline__ float redg_max(float v) {
    v = fmaxf(v, __shfl_xor_sync(0xffffffffu, v, 4));
    v = fmaxf(v, __shfl_xor_sync(0xffffffffu, v, 8));
    v = fmaxf(v, __shfl_xor_sync(0xffffffffu, v, 16));
    return v;
}
__device__ __forceinline__ float redg_min(float v) {
    v = fminf(v, __shfl_xor_sync(0xffffffffu, v, 4));
    v = fminf(v, __shfl_xor_sync(0xffffffffu, v, 8));
    v = fminf(v, __shfl_xor_sync(0xffffffffu, v, 16));
    return v;
}

// ---------------------------------------------------------------------------
// Scratch
// ---------------------------------------------------------------------------
__device__ float g_xallT[(size_t)B_ * N1_ * CPAD];
__device__ float g_oxyz [B_ * N2_ * 4];
__device__ float g_y0[(size_t)M_ * C0];
__device__ float g_y1[(size_t)M_ * C1O];
__device__ float g_part0[2 * NB0T * C0];
__device__ float g_part1[2 * NB1T * C1O];
__device__ float g_part2[2 * NB2T * C2];
__device__ float g_scale0[C0],  g_shift0[C0];
__device__ float g_scale1[C1O], g_shift1[C1O];
__device__ float g_scale2[C2],  g_shift2[C2];
__device__ float g_max2[B_ * N2_ * C2];
__device__ float g_min2[B_ * N2_ * C2];

// ---------------------------------------------------------------------------
// Fused pre: transpose feat+xyz -> [B][N1][72], plus oxyz pack
// ---------------------------------------------------------------------------
__global__ void fused_pre_kernel(const float* __restrict__ in_feature,
                                 const float* __restrict__ in_xyz,
                                 const float* __restrict__ out_xyz) {
    int b  = blockIdx.y;
    int tx = threadIdx.x;
    int ty = threadIdx.y;
    int tid = ty * 32 + tx;

    if (blockIdx.x == N1_ / 32) {
        for (int n2 = tid; n2 < N2_; n2 += 256) {
            int i = b * N2_ + n2;
            g_oxyz[i * 4 + 0] = out_xyz[(b * 3 + 0) * N2_ + n2];
            g_oxyz[i * 4 + 1] = out_xyz[(b * 3 + 1) * N2_ + n2];
            g_oxyz[i * 4 + 2] = out_xyz[(b * 3 + 2) * N2_ + n2];
            g_oxyz[i * 4 + 3] = 0.0f;
        }
        return;
    }

    __shared__ float tile[CPAD][33];
    int n0 = blockIdx.x * 32;
    for (int c = ty; c < CPAD; c += 8) {
        float v;
        if (c < 64)      v = in_feature[((size_t)b * 64 + c) * N1_ + n0 + tx];
        else if (c < 67) v = in_xyz[((size_t)b * 3 + (c - 64)) * N1_ + n0 + tx];
        else             v = 0.0f;
        tile[c][tx] = v;
    }
    __syncthreads();
    for (int e = tid; e < 32 * CPAD; e += 256) {
        int nl = e / CPAD;
        int c  = e % CPAD;
        g_xallT[((size_t)(b * N1_ + n0 + nl)) * CPAD + c] = tile[c][nl];
    }
}

// ---------------------------------------------------------------------------
// GEMM0: gather -> y0 = X(67ch) @ W0^T.  256-row tiles, 8 warps x 32 rows.
// Chain-broken MMA order: all acc touched once per pass (reuse distance 16).
// smem: Wxyz 1K | Whi 8K | Wlo 8K | red 4K = 21504 B
// ---------------------------------------------------------------------------
#define S0_WXYZ  0
#define S0_WHI   1024
#define S0_WLO   9216
#define S0_RED   17408
#define S0_SMEM  21504

__global__ __launch_bounds__(256, 2) void gemm0t_kernel(const int* __restrict__ nbr,
                                                        const float* __restrict__ W0) {
    extern __shared__ char smc[];
    float* Wxyz = (float*)(smc + S0_WXYZ);   // [3][64]
    int tid = threadIdx.x;
    int wid = tid >> 5, lane = tid & 31;

    // W0 feature part [64 cout][64 cin] -> Whi/Wlo swizzled
    for (int e = tid; e < 64 * 64; e += 256) {
        int n = e >> 6, k = e & 63;
        float wv = W0[n * CIN0 + k];
        __nv_bfloat16 h = __float2bfloat16(wv);
        __nv_bfloat16 l = __float2bfloat16(wv - __bfloat162float(h));
        uint32_t byte = (uint32_t)(n * 128 + k * 2);
        uint32_t sw = SMEM_SWIZZLE_128B(byte);
        *(__nv_bfloat16*)(smc + S0_WHI + sw) = h;
        *(__nv_bfloat16*)(smc + S0_WLO + sw) = l;
    }
    if (tid < 192) {
        int c = tid >> 6, n = tid & 63;
        Wxyz[c * 64 + n] = W0[n * CIN0 + 64 + c];
    }

    int g  = lane >> 2;
    int q2 = (lane & 3) * 2;
    int rbase = wid * 32;
    int row0 = blockIdx.x * 256;
    int bb   = row0 >> 15;
    int n2   = ((row0 + rbase) >> 5) & (N2_ - 1);

    // 4 gathered row pointers for this thread (rows g, g+8, g+16, g+24)
    const float* rp[4];
#pragma unroll
    for (int i = 0; i < 4; i++) {
        int idx = nbr[row0 + rbase + g + 8 * i];
        rp[i] = g_xallT + (size_t)(bb * N1_ + idx) * CPAD;
    }
    // xyz for the 4 rows (exact fp32 path)
    float xr[2][2][3];
    {
        const float4 oz = *(const float4*)(g_oxyz + (size_t)(bb * N2_ + n2) * 4);
#pragma unroll
        for (int i = 0; i < 4; i++) {
            float4 p = *(const float4*)(rp[i] + 64);
            xr[i >> 1][i & 1][0] = p.x - oz.x;
            xr[i >> 1][i & 1][1] = p.y - oz.y;
            xr[i >> 1][i & 1][2] = p.z - oz.z;
        }
    }
    __syncthreads();   // W smem ready

    uint32_t whi32 = (uint32_t)__cvta_generic_to_shared(smc + S0_WHI);
    uint32_t wlo32 = (uint32_t)__cvta_generic_to_shared(smc + S0_WLO);
    int rowB7  = (lane & 7) + (((lane >> 4) & 1) << 3);
    int colBof = ((lane >> 3) & 1) << 3;

    float acc[2][8][4];
#pragma unroll
    for (int mt = 0; mt < 2; mt++)
#pragma unroll
        for (int n = 0; n < 8; n++)
#pragma unroll
            for (int j = 0; j < 4; j++) acc[mt][n][j] = 0.0f;

#pragma unroll
    for (int c = 0; c < 4; c++) {
        int kk = c * 16;
        uint32_t ahi[2][4], alo[2][4];
#pragma unroll
        for (int mt = 0; mt < 2; mt++) {
            float2 v0 = *(const float2*)(rp[2 * mt]     + kk + q2);
            float2 v1 = *(const float2*)(rp[2 * mt + 1] + kk + q2);
            float2 v2 = *(const float2*)(rp[2 * mt]     + kk + q2 + 8);
            float2 v3 = *(const float2*)(rp[2 * mt + 1] + kk + q2 + 8);
            split2(v0.x, v0.y, ahi[mt][0], alo[mt][0]);
            split2(v1.x, v1.y, ahi[mt][1], alo[mt][1]);
            split2(v2.x, v2.y, ahi[mt][2], alo[mt][2]);
            split2(v3.x, v3.y, ahi[mt][3], alo[mt][3]);
        }
        // chain-broken order: B-hi for all ntp, then hi·bh pass, lo·bh pass,
        // reload B-lo in place, hi·bl pass.  Same-acc reuse distance = 16.
        uint32_t bfr[4][4];
#pragma unroll
        for (int ntp = 0; ntp < 4; ntp++)
            ldsm_x4(bfr[ntp], sw_off(whi32, ntp * 16 + rowB7, kk + colBof));
#pragma unroll
        for (int ntp = 0; ntp < 4; ntp++)
#pragma unroll
            for (int mt = 0; mt < 2; mt++) {
                mma_bf16(acc[mt][2 * ntp],     ahi[mt], bfr[ntp]);
                mma_bf16(acc[mt][2 * ntp + 1], ahi[mt], bfr[ntp] + 2);
            }
#pragma unroll
        for (int ntp = 0; ntp < 4; ntp++)
#pragma unroll
            for (int mt = 0; mt < 2; mt++) {
                mma_bf16(acc[mt][2 * ntp],     alo[mt], bfr[ntp]);
                mma_bf16(acc[mt][2 * ntp + 1], alo[mt], bfr[ntp] + 2);
            }
#pragma unroll
        for (int ntp = 0; ntp < 4; ntp++)
            ldsm_x4(bfr[ntp], sw_off(wlo32, ntp * 16 + rowB7, kk + colBof));
#pragma unroll
        for (int ntp = 0; ntp < 4; ntp++)
#pragma unroll
            for (int mt = 0; mt < 2; mt++) {
                mma_bf16(acc[mt][2 * ntp],     ahi[mt], bfr[ntp]);
                mma_bf16(acc[mt][2 * ntp + 1], ahi[mt], bfr[ntp] + 2);
            }
    }

    // exact fp32 xyz contribution on fragments
#pragma unroll
    for (int nt = 0; nt < 8; nt++) {
        int c = nt * 8 + q2;
#pragma unroll
        for (int ch = 0; ch < 3; ch++) {
            float w0 = Wxyz[ch * 64 + c], w1 = Wxyz[ch * 64 + c + 1];
#pragma unroll
            for (int mt = 0; mt < 2; mt++) {
                acc[mt][nt][0] = fmaf(xr[mt][0][ch], w0, acc[mt][nt][0]);
                acc[mt][nt][1] = fmaf(xr[mt][0][ch], w1, acc[mt][nt][1]);
                acc[mt][nt][2] = fmaf(xr[mt][1][ch], w0, acc[mt][nt][2]);
                acc[mt][nt][3] = fmaf(xr[mt][1][ch], w1, acc[mt][nt][3]);
            }
        }
    }

    // direct global write of y0
    {
        float* dst = g_y0 + (size_t)blockIdx.x * 256 * 64;
#pragma unroll
        for (int mt = 0; mt < 2; mt++) {
            int r0 = rbase + mt * 16 + g;
#pragma unroll
            for (int nt = 0; nt < 8; nt++) {
                int c = nt * 8 + q2;
                *(float2*)(dst + (size_t)r0 * 64 + c)       = make_float2(acc[mt][nt][0], acc[mt][nt][1]);
                *(float2*)(dst + (size_t)(r0 + 8) * 64 + c) = make_float2(acc[mt][nt][2], acc[mt][nt][3]);
            }
        }
    }

    // stats partials via butterfly
    float* redS = (float*)(smc + S0_RED);  // [8][64]
    float* redQ = redS + 512;
#pragma unroll
    for (int nt = 0; nt < 8; nt++) {
        float a00 = acc[0][nt][0], a01 = acc[0][nt][1], a02 = acc[0][nt][2], a03 = acc[0][nt][3];
        float a10 = acc[1][nt][0], a11 = acc[1][nt][1], a12 = acc[1][nt][2], a13 = acc[1][nt][3];
        float s0 = a00 + a02 + a10 + a12;
        float s1 = a01 + a03 + a11 + a13;
        float q0 = a00 * a00 + a02 * a02 + a10 * a10 + a12 * a12;
        float q1 = a01 * a01 + a03 * a03 + a11 * a11 + a13 * a13;
        s0 = redg_sum(s0); s1 = redg_sum(s1);
        q0 = redg_sum(q0); q1 = redg_sum(q1);
        if (lane < 4) {
            redS[wid * 64 + nt * 8 + q2]     = s0;
            redS[wid * 64 + nt * 8 + q2 + 1] = s1;
            redQ[wid * 64 + nt * 8 + q2]     = q0;
            redQ[wid * 64 + nt * 8 + q2 + 1] = q1;
        }
    }
    __syncthreads();
    if (tid < 128) {
        int which = tid >> 6, c = tid & 63;
        const float* src = which ? redQ : redS;
        float s = 0.0f;
#pragma unroll
        for (int w = 0; w < 8; w++) s += src[w * 64 + c];
        g_part0[(size_t)which * NB0T * C0 + (size_t)blockIdx.x * C0 + c] = s;
    }
}

// ---------------------------------------------------------------------------
// GEMM1: y1 = relu(bn0(y0)) @ W1^T.  256-row tiles, direct-A, chain-broken.
// smem: scb 256 | shb 256 | Whi 8K | Wlo 8K | red 4K = 21504 B
// ---------------------------------------------------------------------------
#define T1_SCB  0
#define T1_SHB  256
#define T1_WHI  1024
#define T1_WLO  9216
#define T1_RED  17408
#define T1_SMEM 21504

__global__ __launch_bounds__(256, 2) void gemm1t_kernel(const float* __restrict__ W1) {
    extern __shared__ char smc[];
    float* scb = (float*)(smc + T1_SCB);
    float* shb = (float*)(smc + T1_SHB);
    int tid = threadIdx.x;
    int wid = tid >> 5, lane = tid & 31;

    if (tid < 64) { scb[tid] = g_scale0[tid]; shb[tid] = g_shift0[tid]; }

    for (int e = tid; e < 64 * 64; e += 256) {
        int n = e >> 6, k = e & 63;
        float wv = W1[e];
        __nv_bfloat16 h = __float2bfloat16(wv);
        __nv_bfloat16 l = __float2bfloat16(wv - __bfloat162float(h));
        uint32_t byte = (uint32_t)(n * 128 + k * 2);
        uint32_t sw = SMEM_SWIZZLE_128B(byte);
        *(__nv_bfloat16*)(smc + T1_WHI + sw) = h;
        *(__nv_bfloat16*)(smc + T1_WLO + sw) = l;
    }

    int g  = lane >> 2;
    int q2 = (lane & 3) * 2;
    int rbase = wid * 32;
    const float* yb = g_y0 + (size_t)blockIdx.x * 256 * 64;
    const float* rp[4];
#pragma unroll
    for (int i = 0; i < 4; i++) rp[i] = yb + (size_t)(rbase + g + 8 * i) * 64;

    __syncthreads();   // W + scb ready

    uint32_t whi32 = (uint32_t)__cvta_generic_to_shared(smc + T1_WHI);
    uint32_t wlo32 = (uint32_t)__cvta_generic_to_shared(smc + T1_WLO);
    int rowB7  = (lane & 7) + (((lane >> 4) & 1) << 3);
    int colBof = ((lane >> 3) & 1) << 3;

    float acc[2][8][4];
#pragma unroll
    for (int mt = 0; mt < 2; mt++)
#pragma unroll
        for (int n = 0; n < 8; n++)
#pragma unroll
            for (int j = 0; j < 4; j++) acc[mt][n][j] = 0.0f;

    float2 buf[2][2][4];
#pragma unroll
    for (int mt = 0; mt < 2; mt++) {
        buf[0][mt][0] = *(const float2*)(rp[2 * mt]     + q2);
        buf[0][mt][1] = *(const float2*)(rp[2 * mt + 1] + q2);
        buf[0][mt][2] = *(const float2*)(rp[2 * mt]     + q2 + 8);
        buf[0][mt][3] = *(const float2*)(rp[2 * mt + 1] + q2 + 8);
    }

#pragma unroll
    for (int c = 0; c < 4; c++) {
        int kk = c * 16;
        if (c < 3) {
            int kn = kk + 16;
#pragma unroll
            for (int mt = 0; mt < 2; mt++) {
                buf[(c + 1) & 1][mt][0] = *(const float2*)(rp[2 * mt]     + kn + q2);
                buf[(c + 1) & 1][mt][1] = *(const float2*)(rp[2 * mt + 1] + kn + q2);
                buf[(c + 1) & 1][mt][2] = *(const float2*)(rp[2 * mt]     + kn + q2 + 8);
                buf[(c + 1) & 1][mt][3] = *(const float2*)(rp[2 * mt + 1] + kn + q2 + 8);
            }
        }
        float2 s0 = *(const float2*)(scb + kk + q2);
        float2 h0 = *(const float2*)(shb + kk + q2);
        float2 s2 = *(const float2*)(scb + kk + q2 + 8);
        float2 h2 = *(const float2*)(shb + kk + q2 + 8);
        uint32_t ahi[2][4], alo[2][4];
#pragma unroll
        for (int mt = 0; mt < 2; mt++) {
            float2 v0 = buf[c & 1][mt][0];
            float2 v1 = buf[c & 1][mt][1];
            float2 v2 = buf[c & 1][mt][2];
            float2 v3 = buf[c & 1][mt][3];
            float x00 = fmaxf(0.f, fmaf(v0.x, s0.x, h0.x));
            float x01 = fmaxf(0.f, fmaf(v0.y, s0.y, h0.y));
            float x10 = fmaxf(0.f, fmaf(v1.x, s0.x, h0.x));
            float x11 = fmaxf(0.f, fmaf(v1.y, s0.y, h0.y));
            float x20 = fmaxf(0.f, fmaf(v2.x, s2.x, h2.x));
            float x21 = fmaxf(0.f, fmaf(v2.y, s2.y, h2.y));
            float x30 = fmaxf(0.f, fmaf(v3.x, s2.x, h2.x));
            float x31 = fmaxf(0.f, fmaf(v3.y, s2.y, h2.y));
            split2(x00, x01, ahi[mt][0], alo[mt][0]);
            split2(x10, x11, ahi[mt][1], alo[mt][1]);
            split2(x20, x21, ahi[mt][2], alo[mt][2]);
            split2(x30, x31, ahi[mt][3], alo[mt][3]);
        }
        // chain-broken MMA order
        uint32_t bfr[4][4];
#pragma unroll
        for (int ntp = 0; ntp < 4; ntp++)
            ldsm_x4(bfr[ntp], sw_off(whi32, ntp * 16 + rowB7, kk + colBof));
#pragma unroll
        for (int ntp = 0; ntp < 4; ntp++)
#pragma unroll
            for (int mt = 0; mt < 2; mt++) {
                mma_bf16(acc[mt][2 * ntp],     ahi[mt], bfr[ntp]);
                mma_bf16(acc[mt][2 * ntp + 1], ahi[mt], bfr[ntp] + 2);
            }
#pragma unroll
        for (int ntp = 0; ntp < 4; ntp++)
#pragma unroll
            for (int mt = 0; mt < 2; mt++) {
                mma_bf16(acc[mt][2 * ntp],     alo[mt], bfr[ntp]);
                mma_bf16(acc[mt][2 * ntp + 1], alo[mt], bfr[ntp] + 2);
            }
#pragma unroll
        for (int ntp = 0; ntp < 4; ntp++)
            ldsm_x4(bfr[ntp], sw_off(wlo32, ntp * 16 + rowB7, kk + colBof));
#pragma unroll
        for (int ntp = 0; ntp < 4; ntp++)
#pragma unroll
            for (int mt = 0; mt < 2; mt++) {
                mma_bf16(acc[mt][2 * ntp],     ahi[mt], bfr[ntp]);
                mma_bf16(acc[mt][2 * ntp + 1], ahi[mt], bfr[ntp] + 2);
            }
    }

    // direct global write of y1
    {
        float* dst = g_y1 + (size_t)blockIdx.x * 256 * 64;
#pragma unroll
        for (int mt = 0; mt < 2; mt++) {
            int r0 = rbase + mt * 16 + g;
#pragma unroll
            for (int nt = 0; nt < 8; nt++) {
                int c = nt * 8 + q2;
                *(float2*)(dst + (size_t)r0 * 64 + c)       = make_float2(acc[mt][nt][0], acc[mt][nt][1]);
                *(float2*)(dst + (size_t)(r0 + 8) * 64 + c) = make_float2(acc[mt][nt][2], acc[mt][nt][3]);
            }
        }
    }

    // stats partials via butterfly
    float* redS = (float*)(smc + T1_RED);
    float* redQ = redS + 512;
#pragma unroll
    for (int nt = 0; nt < 8; nt++) {
        float a00 = acc[0][nt][0], a01 = acc[0][nt][1], a02 = acc[0][nt][2], a03 = acc[0][nt][3];
        float a10 = acc[1][nt][0], a11 = acc[1][nt][1], a12 = acc[1][nt][2], a13 = acc[1][nt][3];
        float s0 = a00 + a02 + a10 + a12;
        float s1 = a01 + a03 + a11 + a13;
        float q0 = a00 * a00 + a02 * a02 + a10 * a10 + a12 * a12;
        float q1 = a01 * a01 + a03 * a03 + a11 * a11 + a13 * a13;
        s0 = redg_sum(s0); s1 = redg_sum(s1);
        q0 = redg_sum(q0); q1 = redg_sum(q1);
        if (lane < 4) {
            redS[wid * 64 + nt * 8 + q2]     = s0;
            redS[wid * 64 + nt * 8 + q2 + 1] = s1;
            redQ[wid * 64 + nt * 8 + q2]     = q0;
            redQ[wid * 64 + nt * 8 + q2 + 1] = q1;
        }
    }
    __syncthreads();
    if (tid < 128) {
        int which = tid >> 6, c = tid & 63;
        const float* src = which ? redQ : redS;
        float s = 0.0f;
#pragma unroll
        for (int w = 0; w < 8; w++) s += src[w * 64 + c];
        g_part1[(size_t)which * NB1T * C1O + (size_t)blockIdx.x * C1O + c] = s;
    }
}

// ---------------------------------------------------------------------------
// GEMM2: y2 = relu(bn1(y1)) @ W2^T, N=128, 128-row tiles, direct-A, chain-broken.
// Epilogue register-resident: shuffle max/min per K-group + stats.
// smem: scb 256 | shb 256 | Whi 16K | Wlo 16K | red 4K = 37888 B
// ---------------------------------------------------------------------------
#define T2_SCB  0
#define T2_SHB  256
#define T2_WHI  1024
#define T2_WLO  17408
#define T2_RED  33792
#define T2_SMEM 37888

__global__ __launch_bounds__(256, 2) void gemm2t_kernel(const float* __restrict__ W2) {
    extern __shared__ char smc[];
    float* scb = (float*)(smc + T2_SCB);
    float* shb = (float*)(smc + T2_SHB);
    int tid = threadIdx.x;
    int wid = tid >> 5, lane = tid & 31;

    if (tid < 64) { scb[tid] = g_scale1[tid]; shb[tid] = g_shift1[tid]; }

    for (int e = tid; e < 128 * 64; e += 256) {
        int n = e >> 6, k = e & 63;
        float wv = W2[e];
        __nv_bfloat16 h = __float2bfloat16(wv);
        __nv_bfloat16 l = __float2bfloat16(wv - __bfloat162float(h));
        uint32_t byte = (uint32_t)(n * 128 + k * 2);
        uint32_t sw = SMEM_SWIZZLE_128B(byte);
        *(__nv_bfloat16*)(smc + T2_WHI + sw) = h;
        *(__nv_bfloat16*)(smc + T2_WLO + sw) = l;
    }

    // 8 warps = 4 (M) x 2 (N): warp rows mw*32..+31 (one K-group), cols nw*64..+63
    int mw = wid & 3, nw = wid >> 2;
    int g  = lane >> 2;
    int q2 = (lane & 3) * 2;
    int rbase = mw * 32;
    const float* yb = g_y1 + (size_t)blockIdx.x * 128 * 64;
    const float* rp[4];
#pragma unroll
    for (int i = 0; i < 4; i++) rp[i] = yb + (size_t)(rbase + g + 8 * i) * 64;

    __syncthreads();

    uint32_t whi32 = (uint32_t)__cvta_generic_to_shared(smc + T2_WHI);
    uint32_t wlo32 = (uint32_t)__cvta_generic_to_shared(smc + T2_WLO);
    int rowB7  = (lane & 7) + (((lane >> 4) & 1) << 3);
    int colBof = ((lane >> 3) & 1) << 3;

    float acc[2][8][4];
#pragma unroll
    for (int mt = 0; mt < 2; mt++)
#pragma unroll
        for (int n = 0; n < 8; n++)
#pragma unroll
            for (int j = 0; j < 4; j++) acc[mt][n][j] = 0.0f;

    float2 buf[2][2][4];
#pragma unroll
    for (int mt = 0; mt < 2; mt++) {
        buf[0][mt][0] = *(const float2*)(rp[2 * mt]     + q2);
        buf[0][mt][1] = *(const float2*)(rp[2 * mt + 1] + q2);
        buf[0][mt][2] = *(const float2*)(rp[2 * mt]     + q2 + 8);
        buf[0][mt][3] = *(const float2*)(rp[2 * mt + 1] + q2 + 8);
    }

#pragma unroll
    for (int c = 0; c < 4; c++) {
        int kk = c * 16;
        if (c < 3) {
            int kn = kk + 16;
#pragma unroll
            for (int mt = 0; mt < 2; mt++) {
                buf[(c + 1) & 1][mt][0] = *(const float2*)(rp[2 * mt]     + kn + q2);
                buf[(c + 1) & 1][mt][1] = *(const float2*)(rp[2 * mt + 1] + kn + q2);
                buf[(c + 1) & 1][mt][2] = *(const float2*)(rp[2 * mt]     + kn + q2 + 8);
                buf[(c + 1) & 1][mt][3] = *(const float2*)(rp[2 * mt + 1] + kn + q2 + 8);
            }
        }
        float2 s0 = *(const float2*)(scb + kk + q2);
        float2 h0 = *(const float2*)(shb + kk + q2);
        float2 s2 = *(const float2*)(scb + kk + q2 + 8);
        float2 h2 = *(const float2*)(shb + kk + q2 + 8);
        uint32_t ahi[2][4], alo[2][4];
#pragma unroll
        for (int mt = 0; mt < 2; mt++) {
            float2 v0 = buf[c & 1][mt][0];
            float2 v1 = buf[c & 1][mt][1];
            float2 v2 = buf[c & 1][mt][2];
            float2 v3 = buf[c & 1][mt][3];
            float x00 = fmaxf(0.f, fmaf(v0.x, s0.x, h0.x));
            float x01 = fmaxf(0.f, fmaf(v0.y, s0.y, h0.y));
            float x10 = fmaxf(0.f, fmaf(v1.x, s0.x, h0.x));
            float x11 = fmaxf(0.f, fmaf(v1.y, s0.y, h0.y));
            float x20 = fmaxf(0.f, fmaf(v2.x, s2.x, h2.x));
            float x21 = fmaxf(0.f, fmaf(v2.y, s2.y, h2.y));
            float x30 = fmaxf(0.f, fmaf(v3.x, s2.x, h2.x));
            float x31 = fmaxf(0.f, fmaf(v3.y, s2.y, h2.y));
            split2(x00, x01, ahi[mt][0], alo[mt][0]);
            split2(x10, x11, ahi[mt][1], alo[mt][1]);
            split2(x20, x21, ahi[mt][2], alo[mt][2]);
            split2(x30, x31, ahi[mt][3], alo[mt][3]);
        }
        // chain-broken MMA order
        uint32_t bfr[4][4];
#pragma unroll
        for (int ntp = 0; ntp < 4; ntp++)
            ldsm_x4(bfr[ntp], sw_off(whi32, nw * 64 + ntp * 16 + rowB7, kk + colBof));
#pragma unroll
        for (int ntp = 0; ntp < 4; ntp++)
#pragma unroll
            for (int mt = 0; mt < 2; mt++) {
                mma_bf16(acc[mt][2 * ntp],     ahi[mt], bfr[ntp]);
                mma_bf16(acc[mt][2 * ntp + 1], ahi[mt], bfr[ntp] + 2);
            }
#pragma unroll
        for (int ntp = 0; ntp < 4; ntp++)
#pragma unroll
            for (int mt = 0; mt < 2; mt++) {
                mma_bf16(acc[mt][2 * ntp],     alo[mt], bfr[ntp]);
                mma_bf16(acc[mt][2 * ntp + 1], alo[mt], bfr[ntp] + 2);
            }
#pragma unroll
        for (int ntp = 0; ntp < 4; ntp++)
            ldsm_x4(bfr[ntp], sw_off(wlo32, nw * 64 + ntp * 16 + rowB7, kk + colBof));
#pragma unroll
        for (int ntp = 0; ntp < 4; ntp++)
#pragma unroll
            for (int mt = 0; mt < 2; mt++) {
                mma_bf16(acc[mt][2 * ntp],     ahi[mt], bfr[ntp]);
                mma_bf16(acc[mt][2 * ntp + 1], ahi[mt], bfr[ntp] + 2);
            }
    }

    // register-resident epilogue: the warp's 32 rows == one K-group
    int row0 = blockIdx.x * 128;
    int b_   = row0 >> 15;
    int n2g  = ((row0 >> 5) & (N2_ - 1)) + mw;
    float* redS = (float*)(smc + T2_RED);   // [4 mw][128]
    float* redQ = redS + 512;
    size_t obase = (size_t)(b_ * N2_ + n2g) * C2;

#pragma unroll
    for (int nt = 0; nt < 8; nt++) {
        float a00 = acc[0][nt][0], a01 = acc[0][nt][1], a02 = acc[0][nt][2], a03 = acc[0][nt][3];
        float a10 = acc[1][nt][0], a11 = acc[1][nt][1], a12 = acc[1][nt][2], a13 = acc[1][nt][3];
        float s0 = a00 + a02 + a10 + a12;
        float s1 = a01 + a03 + a11 + a13;
        float q0 = a00 * a00 + a02 * a02 + a10 * a10 + a12 * a12;
        float q1 = a01 * a01 + a03 * a03 + a11 * a11 + a13 * a13;
        float mx0 = fmaxf(fmaxf(a00, a02), fmaxf(a10, a12));
        float mx1 = fmaxf(fmaxf(a01, a03), fmaxf(a11, a13));
        float mn0 = fminf(fminf(a00, a02), fminf(a10, a12));
        float mn1 = fminf(fminf(a01, a03), fminf(a11, a13));
        s0 = redg_sum(s0); s1 = redg_sum(s1);
        q0 = redg_sum(q0); q1 = redg_sum(q1);
        mx0 = redg_max(mx0); mx1 = redg_max(mx1);
        mn0 = redg_min(mn0); mn1 = redg_min(mn1);
        if (lane < 4) {
            int col = nw * 64 + nt * 8 + q2;
            *(float2*)(g_max2 + obase + col) = make_float2(mx0, mx1);
            *(float2*)(g_min2 + obase + col) = make_float2(mn0, mn1);
            redS[mw * 128 + col]     = s0;
            redS[mw * 128 + col + 1] = s1;
            redQ[mw * 128 + col]     = q0;
            redQ[mw * 128 + col + 1] = q1;
        }
    }
    __syncthreads();
    {
        int which = tid >> 7, c = tid & 127;
        const float* src = which ? redQ : redS;
        float s = src[c] + src[128 + c] + src[256 + c] + src[384 + c];
        g_part2[(size_t)which * NB2T * C2 + (size_t)blockIdx.x * C2 + c] = s;
    }
}

// ---------------------------------------------------------------------------
// Stats finalize
// ---------------------------------------------------------------------------
__global__ void stats_kernel(int layer, const float* __restrict__ gamma,
                             const float* __restrict__ beta) {
    const float* part; int nb, C; float* scale; float* shift;
    if (layer == 0)      { part = g_part0; nb = NB0T; C = C0;  scale = g_scale0; shift = g_shift0; }
    else if (layer == 1) { part = g_part1; nb = NB1T; C = C1O; scale = g_scale1; shift = g_shift1; }
    else                 { part = g_part2; nb = NB2T; C = C2;  scale = g_scale2; shift = g_shift2; }

    __shared__ float shs[256], shq[256];
    int c = blockIdx.x;
    int tid = threadIdx.x;
    float s = 0.0f, q = 0.0f;
    for (int i = tid; i < nb; i += 256) {
        s += part[(size_t)i * C + c];
        q += part[(size_t)(nb + i) * C + c];
    }
    shs[tid] = s; shq[tid] = q;
    __syncthreads();
    for (int off = 128; off > 0; off >>= 1) {
        if (tid < off) { shs[tid] += shs[tid + off]; shq[tid] += shq[tid + off]; }
        __syncthreads();
    }
    if (tid == 0) {
        float mean = shs[0] / CNT_;
        float var  = shq[0] / CNT_ - mean * mean;
        float sc   = gamma[c] * rsqrtf(var + EPS_);
        scale[c] = sc;
        shift[c] = beta[c] - mean * sc;
    }
}

// ---------------------------------------------------------------------------
// Final output
// ---------------------------------------------------------------------------
__global__ void final_kernel(float* __restrict__ out) {
    int o = blockIdx.x * 256 + threadIdx.x;
    if (o >= B_ * C2 * N2_) return;
    int n2 = o & (N2_ - 1);
    int c  = (o >> 10) & (C2 - 1);
    int b  = o >> 17;
    float sc = g_scale2[c], sh = g_shift2[c];
    size_t mi = (size_t)(b * N2_ + n2) * C2 + c;
    float v = (sc >= 0.0f) ? g_max2[mi] : g_min2[mi];
    out[o] = fmaxf(0.0f, fmaf(sc, v, sh));
}

// ---------------------------------------------------------------------------
// Launcher
// ---------------------------------------------------------------------------
extern "C" void kernel_launch(void* const* d_in, const int* in_sizes, int n_in,
                              void* d_out, int out_size) {
    const float* in_xyz     = (const float*)d_in[0];
    const float* out_xyz    = (const float*)d_in[1];
    const float* in_feature = (const float*)d_in[2];
    const int*   nbr        = (const int*)  d_in[3];
    const float* W0 = (const float*)d_in[4];
    const float* g0 = (const float*)d_in[5];
    const float* b0 = (const float*)d_in[6];
    const float* W1 = (const float*)d_in[7];
    const float* g1 = (const float*)d_in[8];
    const float* b1 = (const float*)d_in[9];
    const float* W2 = (const float*)d_in[10];
    const float* g2 = (const float*)d_in[11];
    const float* b2 = (const float*)d_in[12];
    float* out = (float*)d_out;

    cudaFuncSetAttribute(gemm0t_kernel, cudaFuncAttributeMaxDynamicSharedMemorySize, S0_SMEM);
    cudaFuncSetAttribute(gemm1t_kernel, cudaFuncAttributeMaxDynamicSharedMemorySize, T1_SMEM);
    cudaFuncSetAttribute(gemm2t_kernel, cudaFuncAttributeMaxDynamicSharedMemorySize, T2_SMEM);

    // launch order keeps gemm2t at index 5 for the fixed ncu -s 5 -c 1 window
    fused_pre_kernel<<<dim3(N1_ / 32 + 1, B_), dim3(32, 8)>>>(in_feature, in_xyz, out_xyz);

    gemm0t_kernel<<<NB0T, 256, S0_SMEM>>>(nbr, W0);
    stats_kernel<<<C0, 256>>>(0, g0, b0);

    gemm1t_kernel<<<NB1T, 256, T1_SMEM>>>(W1);
    stats_kernel<<<C1O, 256>>>(1, g1, b1);

    gemm2t_kernel<<<NB2T, 256, T2_SMEM>>>(W2);
    stats_kernel<<<C2, 256>>>(2, g2, b2);

    final_kernel<<<(B_ * C2 * N2_ + 255) / 256, 256>>>(out);
}

// round 17
// speedup vs baseline: 1.0027x; 1.0027x over previous
#include <cuda_runtime.h>
#include <cuda_bf16.h>
#include <math.h>
#include <cstdint>

// ---------------------------------------------------------------------------
// Problem constants
// ---------------------------------------------------------------------------
#define B_    16
#define N1_   4096
#define N2_   1024
#define KNB   32
#define CIN0  67
#define CPAD  72              // xallT rows padded to 288B
#define C0    64
#define C1O   64
#define C2    128
#define M_    (B_ * N2_ * KNB)     // 524288
#define NB0T  (M_ / 256)           // 2048 (gemm0 blocks)
#define NB1P  (M_ / 128)           // 4096 partial tiles (layer1)
#define NB2P  (M_ / 128)           // 4096 partial tiles (layer2)
#define TILES 8                    // tiles per CTA in pipelined gemms
#define NB1G  (M_ / (128 * TILES)) // 512 blocks
#define NB2G  (M_ / (128 * TILES)) // 512 blocks
#define CNT_  524288.0f
#define EPS_  1e-5f

#define XSTRIDE_F 68               // floats per smem row (272 B)
#define XSTAGE_B  (128 * 272)      // 34816 B per stage

// ---------------------------------------------------------------------------
// mma.sync / ldmatrix / cp.async helpers (baseline PTX, works on compute_103)
// ---------------------------------------------------------------------------
__device__ __forceinline__ void mma_bf16(float* d, const uint32_t* a, const uint32_t* b) {
    asm volatile(
        "mma.sync.aligned.m16n8k16.row.col.f32.bf16.bf16.f32 "
        "{%0,%1,%2,%3}, {%4,%5,%6,%7}, {%8,%9}, {%0,%1,%2,%3};"
        : "+f"(d[0]), "+f"(d[1]), "+f"(d[2]), "+f"(d[3])
        : "r"(a[0]), "r"(a[1]), "r"(a[2]), "r"(a[3]), "r"(b[0]), "r"(b[1]));
}
__device__ __forceinline__ void ldsm_x4(uint32_t* r, uint32_t addr) {
    asm volatile("ldmatrix.sync.aligned.m8n8.x4.shared.b16 {%0,%1,%2,%3}, [%4];"
        : "=r"(r[0]), "=r"(r[1]), "=r"(r[2]), "=r"(r[3]) : "r"(addr));
}
__device__ __forceinline__ void cp16(uint32_t dst, const void* src) {
    asm volatile("cp.async.cg.shared.global [%0], [%1], 16;" :: "r"(dst), "l"(src));
}
#define CP_COMMIT() asm volatile("cp.async.commit_group;" ::: "memory")
#define CP_WAIT1()  asm volatile("cp.async.wait_group 1;" ::: "memory")
#define CP_WAIT0()  asm volatile("cp.async.wait_group 0;" ::: "memory")

// swizzled smem address for bf16 weight tiles with 128-byte rows
__device__ __forceinline__ uint32_t sw_off(uint32_t base32, int row, int col) {
    uint32_t byte = (uint32_t)(row * 128 + col * 2);
    byte ^= (byte >> 3) & 0x70;
    return base32 + byte;
}
#define SMEM_SWIZZLE_128B(b) ((b) ^ (((b) >> 3) & 0x70))

// bf16 hi/lo split of two fp32 values, packed as bf16x2 words
__device__ __forceinline__ void split2(float a, float b, uint32_t& hi, uint32_t& lo) {
    __nv_bfloat16 ha = __float2bfloat16(a), hb = __float2bfloat16(b);
    __nv_bfloat16 la = __float2bfloat16(a - __bfloat162float(ha));
    __nv_bfloat16 lb = __float2bfloat16(b - __bfloat162float(hb));
    hi = (uint32_t)__bfloat16_as_ushort(ha) | ((uint32_t)__bfloat16_as_ushort(hb) << 16);
    lo = (uint32_t)__bfloat16_as_ushort(la) | ((uint32_t)__bfloat16_as_ushort(lb) << 16);
}

// butterfly reductions over the g-lanes (lane bits 2..4)
__device__ __forceinline__ float redg_sum(float v) {
    v += __shfl_xor_sync(0xffffffffu, v, 4);
    v += __shfl_xor_sync(0xffffffffu, v, 8);
    v += __shfl_xor_sync(0xffffffffu, v, 16);
    return v;
}
__device__ __forceinline__ float redg_max(float v) {
    v = fmaxf(v, __shfl_xor_sync(0xffffffffu, v, 4));
    v = fmaxf(v, __shfl_xor_sync(0xffffffffu, v, 8));
    v = fmaxf(v, __shfl_xor_sync(0xffffffffu, v, 16));
    return v;
}
__device__ __forceinline__ float redg_min(float v) {
    v = fminf(v, __shfl_xor_sync(0xffffffffu, v, 4));
    v = fminf(v, __shfl_xor_sync(0xffffffffu, v, 8));
    v = fminf(v, __shfl_xor_sync(0xffffffffu, v, 16));
    return v;
}

// ---------------------------------------------------------------------------
// Scratch
// ---------------------------------------------------------------------------
__device__ float g_xallT[(size_t)B_ * N1_ * CPAD];
__device__ float g_oxyz [B_ * N2_ * 4];
__device__ float g_y0[(size_t)M_ * C0];
__device__ float g_y1[(size_t)M_ * C1O];
__device__ float g_part0[2 * NB0T * C0];
__device__ float g_part1[2 * NB1P * C1O];
__device__ float g_part2[2 * NB2P * C2];
__device__ float g_scale0[C0],  g_shift0[C0];
__device__ float g_scale1[C1O], g_shift1[C1O];
__device__ float g_scale2[C2],  g_shift2[C2];
__device__ float g_max2[B_ * N2_ * C2];
__device__ float g_min2[B_ * N2_ * C2];

// ---------------------------------------------------------------------------
// Fused pre: transpose feat+xyz -> [B][N1][72], plus oxyz pack
// ---------------------------------------------------------------------------
__global__ void fused_pre_kernel(const float* __restrict__ in_feature,
                                 const float* __restrict__ in_xyz,
                                 const float* __restrict__ out_xyz) {
    int b  = blockIdx.y;
    int tx = threadIdx.x;
    int ty = threadIdx.y;
    int tid = ty * 32 + tx;

    if (blockIdx.x == N1_ / 32) {
        for (int n2 = tid; n2 < N2_; n2 += 256) {
            int i = b * N2_ + n2;
            g_oxyz[i * 4 + 0] = out_xyz[(b * 3 + 0) * N2_ + n2];
            g_oxyz[i * 4 + 1] = out_xyz[(b * 3 + 1) * N2_ + n2];
            g_oxyz[i * 4 + 2] = out_xyz[(b * 3 + 2) * N2_ + n2];
            g_oxyz[i * 4 + 3] = 0.0f;
        }
        return;
    }

    __shared__ float tile[CPAD][33];
    int n0 = blockIdx.x * 32;
    for (int c = ty; c < CPAD; c += 8) {
        float v;
        if (c < 64)      v = in_feature[((size_t)b * 64 + c) * N1_ + n0 + tx];
        else if (c < 67) v = in_xyz[((size_t)b * 3 + (c - 64)) * N1_ + n0 + tx];
        else             v = 0.0f;
        tile[c][tx] = v;
    }
    __syncthreads();
    for (int e = tid; e < 32 * CPAD; e += 256) {
        int nl = e / CPAD;
        int c  = e % CPAD;
        g_xallT[((size_t)(b * N1_ + n0 + nl)) * CPAD + c] = tile[c][nl];
    }
}

// ---------------------------------------------------------------------------
// GEMM0: gather -> y0 = X(67ch) @ W0^T.  256-row tiles (unchanged this round).
// smem: Wxyz 1K | Whi 8K | Wlo 8K | red 4K = 21504 B
// ---------------------------------------------------------------------------
#define S0_WXYZ  0
#define S0_WHI   1024
#define S0_WLO   9216
#define S0_RED   17408
#define S0_SMEM  21504

__global__ __launch_bounds__(256, 2) void gemm0t_kernel(const int* __restrict__ nbr,
                                                        const float* __restrict__ W0) {
    extern __shared__ char smc[];
    float* Wxyz = (float*)(smc + S0_WXYZ);
    int tid = threadIdx.x;
    int wid = tid >> 5, lane = tid & 31;

    for (int e = tid; e < 64 * 64; e += 256) {
        int n = e >> 6, k = e & 63;
        float wv = W0[n * CIN0 + k];
        __nv_bfloat16 h = __float2bfloat16(wv);
        __nv_bfloat16 l = __float2bfloat16(wv - __bfloat162float(h));
        uint32_t byte = (uint32_t)(n * 128 + k * 2);
        uint32_t sw = SMEM_SWIZZLE_128B(byte);
        *(__nv_bfloat16*)(smc + S0_WHI + sw) = h;
        *(__nv_bfloat16*)(smc + S0_WLO + sw) = l;
    }
    if (tid < 192) {
        int c = tid >> 6, n = tid & 63;
        Wxyz[c * 64 + n] = W0[n * CIN0 + 64 + c];
    }

    int g  = lane >> 2;
    int q2 = (lane & 3) * 2;
    int rbase = wid * 32;
    int row0 = blockIdx.x * 256;
    int bb   = row0 >> 15;
    int n2   = ((row0 + rbase) >> 5) & (N2_ - 1);

    const float* rp[4];
#pragma unroll
    for (int i = 0; i < 4; i++) {
        int idx = nbr[row0 + rbase + g + 8 * i];
        rp[i] = g_xallT + (size_t)(bb * N1_ + idx) * CPAD;
    }
    float xr[2][2][3];
    {
        const float4 oz = *(const float4*)(g_oxyz + (size_t)(bb * N2_ + n2) * 4);
#pragma unroll
        for (int i = 0; i < 4; i++) {
            float4 p = *(const float4*)(rp[i] + 64);
            xr[i >> 1][i & 1][0] = p.x - oz.x;
            xr[i >> 1][i & 1][1] = p.y - oz.y;
            xr[i >> 1][i & 1][2] = p.z - oz.z;
        }
    }
    __syncthreads();

    uint32_t whi32 = (uint32_t)__cvta_generic_to_shared(smc + S0_WHI);
    uint32_t wlo32 = (uint32_t)__cvta_generic_to_shared(smc + S0_WLO);
    int rowB7  = (lane & 7) + (((lane >> 4) & 1) << 3);
    int colBof = ((lane >> 3) & 1) << 3;

    float acc[2][8][4];
#pragma unroll
    for (int mt = 0; mt < 2; mt++)
#pragma unroll
        for (int n = 0; n < 8; n++)
#pragma unroll
            for (int j = 0; j < 4; j++) acc[mt][n][j] = 0.0f;

#pragma unroll
    for (int c = 0; c < 4; c++) {
        int kk = c * 16;
        uint32_t ahi[2][4], alo[2][4];
#pragma unroll
        for (int mt = 0; mt < 2; mt++) {
            float2 v0 = *(const float2*)(rp[2 * mt]     + kk + q2);
            float2 v1 = *(const float2*)(rp[2 * mt + 1] + kk + q2);
            float2 v2 = *(const float2*)(rp[2 * mt]     + kk + q2 + 8);
            float2 v3 = *(const float2*)(rp[2 * mt + 1] + kk + q2 + 8);
            split2(v0.x, v0.y, ahi[mt][0], alo[mt][0]);
            split2(v1.x, v1.y, ahi[mt][1], alo[mt][1]);
            split2(v2.x, v2.y, ahi[mt][2], alo[mt][2]);
            split2(v3.x, v3.y, ahi[mt][3], alo[mt][3]);
        }
        uint32_t bfr[4][4];
#pragma unroll
        for (int ntp = 0; ntp < 4; ntp++)
            ldsm_x4(bfr[ntp], sw_off(whi32, ntp * 16 + rowB7, kk + colBof));
#pragma unroll
        for (int ntp = 0; ntp < 4; ntp++)
#pragma unroll
            for (int mt = 0; mt < 2; mt++) {
                mma_bf16(acc[mt][2 * ntp],     ahi[mt], bfr[ntp]);
                mma_bf16(acc[mt][2 * ntp + 1], ahi[mt], bfr[ntp] + 2);
            }
#pragma unroll
        for (int ntp = 0; ntp < 4; ntp++)
#pragma unroll
            for (int mt = 0; mt < 2; mt++) {
                mma_bf16(acc[mt][2 * ntp],     alo[mt], bfr[ntp]);
                mma_bf16(acc[mt][2 * ntp + 1], alo[mt], bfr[ntp] + 2);
            }
#pragma unroll
        for (int ntp = 0; ntp < 4; ntp++)
            ldsm_x4(bfr[ntp], sw_off(wlo32, ntp * 16 + rowB7, kk + colBof));
#pragma unroll
        for (int ntp = 0; ntp < 4; ntp++)
#pragma unroll
            for (int mt = 0; mt < 2; mt++) {
                mma_bf16(acc[mt][2 * ntp],     ahi[mt], bfr[ntp]);
                mma_bf16(acc[mt][2 * ntp + 1], ahi[mt], bfr[ntp] + 2);
            }
    }

#pragma unroll
    for (int nt = 0; nt < 8; nt++) {
        int c = nt * 8 + q2;
#pragma unroll
        for (int ch = 0; ch < 3; ch++) {
            float w0 = Wxyz[ch * 64 + c], w1 = Wxyz[ch * 64 + c + 1];
#pragma unroll
            for (int mt = 0; mt < 2; mt++) {
                acc[mt][nt][0] = fmaf(xr[mt][0][ch], w0, acc[mt][nt][0]);
                acc[mt][nt][1] = fmaf(xr[mt][0][ch], w1, acc[mt][nt][1]);
                acc[mt][nt][2] = fmaf(xr[mt][1][ch], w0, acc[mt][nt][2]);
                acc[mt][nt][3] = fmaf(xr[mt][1][ch], w1, acc[mt][nt][3]);
            }
        }
    }

    {
        float* dst = g_y0 + (size_t)blockIdx.x * 256 * 64;
#pragma unroll
        for (int mt = 0; mt < 2; mt++) {
            int r0 = rbase + mt * 16 + g;
#pragma unroll
            for (int nt = 0; nt < 8; nt++) {
                int c = nt * 8 + q2;
                *(float2*)(dst + (size_t)r0 * 64 + c)       = make_float2(acc[mt][nt][0], acc[mt][nt][1]);
                *(float2*)(dst + (size_t)(r0 + 8) * 64 + c) = make_float2(acc[mt][nt][2], acc[mt][nt][3]);
            }
        }
    }

    float* redS = (float*)(smc + S0_RED);
    float* redQ = redS + 512;
#pragma unroll
    for (int nt = 0; nt < 8; nt++) {
        float a00 = acc[0][nt][0], a01 = acc[0][nt][1], a02 = acc[0][nt][2], a03 = acc[0][nt][3];
        float a10 = acc[1][nt][0], a11 = acc[1][nt][1], a12 = acc[1][nt][2], a13 = acc[1][nt][3];
        float s0 = a00 + a02 + a10 + a12;
        float s1 = a01 + a03 + a11 + a13;
        float q0 = a00 * a00 + a02 * a02 + a10 * a10 + a12 * a12;
        float q1 = a01 * a01 + a03 * a03 + a11 * a11 + a13 * a13;
        s0 = redg_sum(s0); s1 = redg_sum(s1);
        q0 = redg_sum(q0); q1 = redg_sum(q1);
        if (lane < 4) {
            redS[wid * 64 + nt * 8 + q2]     = s0;
            redS[wid * 64 + nt * 8 + q2 + 1] = s1;
            redQ[wid * 64 + nt * 8 + q2]     = q0;
            redQ[wid * 64 + nt * 8 + q2 + 1] = q1;
        }
    }
    __syncthreads();
    if (tid < 128) {
        int which = tid >> 6, c = tid & 63;
        const float* src = which ? redQ : redS;
        float s = 0.0f;
#pragma unroll
        for (int w = 0; w < 8; w++) s += src[w * 64 + c];
        g_part0[(size_t)which * NB0T * C0 + (size_t)blockIdx.x * C0 + c] = s;
    }
}

// ---------------------------------------------------------------------------
// GEMM1 (pipelined): y1 = relu(bn0(y0)) @ W1^T.
// 512 CTAs x 8 tiles of 128 rows; 2-stage cp.async smem pipeline.
// smem: scb/shb 1K | Whi 8K | Wlo 8K | red 4K | X 2x34816 = 91136 B
// ---------------------------------------------------------------------------
#define T1_SCB  0
#define T1_SHB  256
#define T1_WHI  1024
#define T1_WLO  9216
#define T1_RED  17408
#define T1_X0   21504
#define T1_SMEM (T1_X0 + 2 * XSTAGE_B)   // 91136

__global__ __launch_bounds__(256, 2) void gemm1t_kernel(const float* __restrict__ W1) {
    extern __shared__ char smc[];
    float* scb = (float*)(smc + T1_SCB);
    float* shb = (float*)(smc + T1_SHB);
    int tid = threadIdx.x;
    int wid = tid >> 5, lane = tid & 31;

    if (tid < 64) { scb[tid] = g_scale0[tid]; shb[tid] = g_shift0[tid]; }
    for (int e = tid; e < 64 * 64; e += 256) {
        int n = e >> 6, k = e & 63;
        float wv = W1[e];
        __nv_bfloat16 h = __float2bfloat16(wv);
        __nv_bfloat16 l = __float2bfloat16(wv - __bfloat162float(h));
        uint32_t byte = (uint32_t)(n * 128 + k * 2);
        uint32_t sw = SMEM_SWIZZLE_128B(byte);
        *(__nv_bfloat16*)(smc + T1_WHI + sw) = h;
        *(__nv_bfloat16*)(smc + T1_WLO + sw) = l;
    }

    uint32_t x32 = (uint32_t)__cvta_generic_to_shared(smc + T1_X0);
    int tile0 = blockIdx.x * TILES;

    // prologue: prefetch tiles 0 and 1
#pragma unroll
    for (int s = 0; s < 2; s++) {
        const char* src = (const char*)(g_y0 + (size_t)(tile0 + s) * 128 * 64);
        uint32_t dst = x32 + s * XSTAGE_B;
#pragma unroll
        for (int i = 0; i < 8; i++) {
            int c = tid + i * 256;
            int row = c >> 4, off = (c & 15) * 16;
            cp16(dst + row * 272 + off, src + row * 256 + off);
        }
        CP_COMMIT();
    }

    uint32_t whi32 = (uint32_t)__cvta_generic_to_shared(smc + T1_WHI);
    uint32_t wlo32 = (uint32_t)__cvta_generic_to_shared(smc + T1_WLO);
    int g  = lane >> 2;
    int q2 = (lane & 3) * 2;
    int rowB7  = (lane & 7) + (((lane >> 4) & 1) << 3);
    int colBof = ((lane >> 3) & 1) << 3;
    int r0 = wid * 16 + g;          // warp covers 16 rows
    float* redS = (float*)(smc + T1_RED);
    float* redQ = redS + 512;

#pragma unroll 1
    for (int t = 0; t < TILES; t++) {
        if (t + 1 < TILES) { CP_WAIT1(); } else { CP_WAIT0(); }
        __syncthreads();
        const float* xs = (const float*)(smc + T1_X0 + (t & 1) * XSTAGE_B);

        float acc[8][4];
#pragma unroll
        for (int n = 0; n < 8; n++)
#pragma unroll
            for (int j = 0; j < 4; j++) acc[n][j] = 0.0f;

#pragma unroll
        for (int c = 0; c < 4; c++) {
            int kk = c * 16;
            float2 v0 = *(const float2*)(xs + r0 * XSTRIDE_F + kk + q2);
            float2 v1 = *(const float2*)(xs + (r0 + 8) * XSTRIDE_F + kk + q2);
            float2 v2 = *(const float2*)(xs + r0 * XSTRIDE_F + kk + q2 + 8);
            float2 v3 = *(const float2*)(xs + (r0 + 8) * XSTRIDE_F + kk + q2 + 8);
            float2 s0 = *(const float2*)(scb + kk + q2);
            float2 h0 = *(const float2*)(shb + kk + q2);
            float2 s2 = *(const float2*)(scb + kk + q2 + 8);
            float2 h2 = *(const float2*)(shb + kk + q2 + 8);
            uint32_t ahi[4], alo[4];
            split2(fmaxf(0.f, fmaf(v0.x, s0.x, h0.x)), fmaxf(0.f, fmaf(v0.y, s0.y, h0.y)), ahi[0], alo[0]);
            split2(fmaxf(0.f, fmaf(v1.x, s0.x, h0.x)), fmaxf(0.f, fmaf(v1.y, s0.y, h0.y)), ahi[1], alo[1]);
            split2(fmaxf(0.f, fmaf(v2.x, s2.x, h2.x)), fmaxf(0.f, fmaf(v2.y, s2.y, h2.y)), ahi[2], alo[2]);
            split2(fmaxf(0.f, fmaf(v3.x, s2.x, h2.x)), fmaxf(0.f, fmaf(v3.y, s2.y, h2.y)), ahi[3], alo[3]);

            uint32_t bfr[4][4];
#pragma unroll
            for (int ntp = 0; ntp < 4; ntp++)
                ldsm_x4(bfr[ntp], sw_off(whi32, ntp * 16 + rowB7, kk + colBof));
#pragma unroll
            for (int ntp = 0; ntp < 4; ntp++) {
                mma_bf16(acc[2 * ntp],     ahi, bfr[ntp]);
                mma_bf16(acc[2 * ntp + 1], ahi, bfr[ntp] + 2);
            }
#pragma unroll
            for (int ntp = 0; ntp < 4; ntp++) {
                mma_bf16(acc[2 * ntp],     alo, bfr[ntp]);
                mma_bf16(acc[2 * ntp + 1], alo, bfr[ntp] + 2);
            }
#pragma unroll
            for (int ntp = 0; ntp < 4; ntp++)
                ldsm_x4(bfr[ntp], sw_off(wlo32, ntp * 16 + rowB7, kk + colBof));
#pragma unroll
            for (int ntp = 0; ntp < 4; ntp++) {
                mma_bf16(acc[2 * ntp],     ahi, bfr[ntp]);
                mma_bf16(acc[2 * ntp + 1], ahi, bfr[ntp] + 2);
            }
        }
        __syncthreads();   // all warps done reading this stage

        // refill the just-freed stage with tile t+2 (overlaps epilogue)
        if (t + 2 < TILES) {
            const char* src = (const char*)(g_y0 + (size_t)(tile0 + t + 2) * 128 * 64);
            uint32_t dst = x32 + (t & 1) * XSTAGE_B;
#pragma unroll
            for (int i = 0; i < 8; i++) {
                int c = tid + i * 256;
                int row = c >> 4, off = (c & 15) * 16;
                cp16(dst + row * 272 + off, src + row * 256 + off);
            }
            CP_COMMIT();
        }

        // epilogue: y1 write + stats partials
        {
            float* dst = g_y1 + (size_t)(tile0 + t) * 128 * 64;
#pragma unroll
            for (int nt = 0; nt < 8; nt++) {
                int c = nt * 8 + q2;
                *(float2*)(dst + (size_t)r0 * 64 + c)       = make_float2(acc[nt][0], acc[nt][1]);
                *(float2*)(dst + (size_t)(r0 + 8) * 64 + c) = make_float2(acc[nt][2], acc[nt][3]);
            }
        }
#pragma unroll
        for (int nt = 0; nt < 8; nt++) {
            float s0 = acc[nt][0] + acc[nt][2];
            float s1 = acc[nt][1] + acc[nt][3];
            float q0 = acc[nt][0] * acc[nt][0] + acc[nt][2] * acc[nt][2];
            float q1 = acc[nt][1] * acc[nt][1] + acc[nt][3] * acc[nt][3];
            s0 = redg_sum(s0); s1 = redg_sum(s1);
            q0 = redg_sum(q0); q1 = redg_sum(q1);
            if (lane < 4) {
                redS[wid * 64 + nt * 8 + q2]     = s0;
                redS[wid * 64 + nt * 8 + q2 + 1] = s1;
                redQ[wid * 64 + nt * 8 + q2]     = q0;
                redQ[wid * 64 + nt * 8 + q2 + 1] = q1;
            }
        }
        __syncthreads();
        if (tid < 128) {
            int which = tid >> 6, c = tid & 63;
            const float* src = which ? redQ : redS;
            float s = 0.0f;
#pragma unroll
            for (int w = 0; w < 8; w++) s += src[w * 64 + c];
            g_part1[(size_t)which * NB1P * C1O + (size_t)(tile0 + t) * C1O + c] = s;
        }
    }
}

// ---------------------------------------------------------------------------
// GEMM2 (pipelined): y2 = relu(bn1(y1)) @ W2^T, N=128.
// 512 CTAs x 8 tiles of 128 rows; 8 warps = 4(M)x2(N); register max/min epi.
// smem: scb/shb 1K | Whi 16K | Wlo 16K | red 4K | X 2x34816 = 107520 B
// ---------------------------------------------------------------------------
#define T2_SCB  0
#define T2_SHB  256
#define T2_WHI  1024
#define T2_WLO  17408
#define T2_RED  33792
#define T2_X0   37888
#define T2_SMEM (T2_X0 + 2 * XSTAGE_B)   // 107520

__global__ __launch_bounds__(256, 2) void gemm2t_kernel(const float* __restrict__ W2) {
    extern __shared__ char smc[];
    float* scb = (float*)(smc + T2_SCB);
    float* shb = (float*)(smc + T2_SHB);
    int tid = threadIdx.x;
    int wid = tid >> 5, lane = tid & 31;

    if (tid < 64) { scb[tid] = g_scale1[tid]; shb[tid] = g_shift1[tid]; }
    for (int e = tid; e < 128 * 64; e += 256) {
        int n = e >> 6, k = e & 63;
        float wv = W2[e];
        __nv_bfloat16 h = __float2bfloat16(wv);
        __nv_bfloat16 l = __float2bfloat16(wv - __bfloat162float(h));
        uint32_t byte = (uint32_t)(n * 128 + k * 2);
        uint32_t sw = SMEM_SWIZZLE_128B(byte);
        *(__nv_bfloat16*)(smc + T2_WHI + sw) = h;
        *(__nv_bfloat16*)(smc + T2_WLO + sw) = l;
    }

    uint32_t x32 = (uint32_t)__cvta_generic_to_shared(smc + T2_X0);
    int tile0 = blockIdx.x * TILES;

#pragma unroll
    for (int s = 0; s < 2; s++) {
        const char* src = (const char*)(g_y1 + (size_t)(tile0 + s) * 128 * 64);
        uint32_t dst = x32 + s * XSTAGE_B;
#pragma unroll
        for (int i = 0; i < 8; i++) {
            int c = tid + i * 256;
            int row = c >> 4, off = (c & 15) * 16;
            cp16(dst + row * 272 + off, src + row * 256 + off);
        }
        CP_COMMIT();
    }

    uint32_t whi32 = (uint32_t)__cvta_generic_to_shared(smc + T2_WHI);
    uint32_t wlo32 = (uint32_t)__cvta_generic_to_shared(smc + T2_WLO);
    int mw = wid & 3, nw = wid >> 2;
    int g  = lane >> 2;
    int q2 = (lane & 3) * 2;
    int rowB7  = (lane & 7) + (((lane >> 4) & 1) << 3);
    int colBof = ((lane >> 3) & 1) << 3;
    int rA0 = mw * 32 + g;            // rows rA0, rA0+8 (mt0); +16, +24 (mt1)
    float* redS = (float*)(smc + T2_RED);
    float* redQ = redS + 512;

#pragma unroll 1
    for (int t = 0; t < TILES; t++) {
        if (t + 1 < TILES) { CP_WAIT1(); } else { CP_WAIT0(); }
        __syncthreads();
        const float* xs = (const float*)(smc + T2_X0 + (t & 1) * XSTAGE_B);

        float acc[2][8][4];
#pragma unroll
        for (int mt = 0; mt < 2; mt++)
#pragma unroll
            for (int n = 0; n < 8; n++)
#pragma unroll
                for (int j = 0; j < 4; j++) acc[mt][n][j] = 0.0f;

#pragma unroll
        for (int c = 0; c < 4; c++) {
            int kk = c * 16;
            float2 s0 = *(const float2*)(scb + kk + q2);
            float2 h0 = *(const float2*)(shb + kk + q2);
            float2 s2 = *(const float2*)(scb + kk + q2 + 8);
            float2 h2 = *(const float2*)(shb + kk + q2 + 8);
            uint32_t ahi[2][4], alo[2][4];
#pragma unroll
            for (int mt = 0; mt < 2; mt++) {
                int rr = rA0 + mt * 16;
                float2 v0 = *(const float2*)(xs + rr * XSTRIDE_F + kk + q2);
                float2 v1 = *(const float2*)(xs + (rr + 8) * XSTRIDE_F + kk + q2);
                float2 v2 = *(const float2*)(xs + rr * XSTRIDE_F + kk + q2 + 8);
                float2 v3 = *(const float2*)(xs + (rr + 8) * XSTRIDE_F + kk + q2 + 8);
                split2(fmaxf(0.f, fmaf(v0.x, s0.x, h0.x)), fmaxf(0.f, fmaf(v0.y, s0.y, h0.y)), ahi[mt][0], alo[mt][0]);
                split2(fmaxf(0.f, fmaf(v1.x, s0.x, h0.x)), fmaxf(0.f, fmaf(v1.y, s0.y, h0.y)), ahi[mt][1], alo[mt][1]);
                split2(fmaxf(0.f, fmaf(v2.x, s2.x, h2.x)), fmaxf(0.f, fmaf(v2.y, s2.y, h2.y)), ahi[mt][2], alo[mt][2]);
                split2(fmaxf(0.f, fmaf(v3.x, s2.x, h2.x)), fmaxf(0.f, fmaf(v3.y, s2.y, h2.y)), ahi[mt][3], alo[mt][3]);
            }
            uint32_t bfr[4][4];
#pragma unroll
            for (int ntp = 0; ntp < 4; ntp++)
                ldsm_x4(bfr[ntp], sw_off(whi32, nw * 64 + ntp * 16 + rowB7, kk + colBof));
#pragma unroll
            for (int ntp = 0; ntp < 4; ntp++)
#pragma unroll
                for (int mt = 0; mt < 2; mt++) {
                    mma_bf16(acc[mt][2 * ntp],     ahi[mt], bfr[ntp]);
                    mma_bf16(acc[mt][2 * ntp + 1], ahi[mt], bfr[ntp] + 2);
                }
#pragma unroll
            for (int ntp = 0; ntp < 4; ntp++)
#pragma unroll
                for (int mt = 0; mt < 2; mt++) {
                    mma_bf16(acc[mt][2 * ntp],     alo[mt], bfr[ntp]);
                    mma_bf16(acc[mt][2 * ntp + 1], alo[mt], bfr[ntp] + 2);
                }
#pragma unroll
            for (int ntp = 0; ntp < 4; ntp++)
                ldsm_x4(bfr[ntp], sw_off(wlo32, nw * 64 + ntp * 16 + rowB7, kk + colBof));
#pragma unroll
            for (int ntp = 0; ntp < 4; ntp++)
#pragma unroll
                for (int mt = 0; mt < 2; mt++) {
                    mma_bf16(acc[mt][2 * ntp],     ahi[mt], bfr[ntp]);
                    mma_bf16(acc[mt][2 * ntp + 1], ahi[mt], bfr[ntp] + 2);
                }
        }
        __syncthreads();   // all warps done reading this stage

        if (t + 2 < TILES) {
            const char* src = (const char*)(g_y1 + (size_t)(tile0 + t + 2) * 128 * 64);
            uint32_t dst = x32 + (t & 1) * XSTAGE_B;
#pragma unroll
            for (int i = 0; i < 8; i++) {
                int c = tid + i * 256;
                int row = c >> 4, off = (c & 15) * 16;
                cp16(dst + row * 272 + off, src + row * 256 + off);
            }
            CP_COMMIT();
        }

        // register-resident epilogue: warp's 32 rows == one K-group
        int row0 = (tile0 + t) * 128;
        int b_   = row0 >> 15;
        int n2g  = ((row0 >> 5) & (N2_ - 1)) + mw;
        size_t obase = (size_t)(b_ * N2_ + n2g) * C2;
#pragma unroll
        for (int nt = 0; nt < 8; nt++) {
            float a00 = acc[0][nt][0], a01 = acc[0][nt][1], a02 = acc[0][nt][2], a03 = acc[0][nt][3];
            float a10 = acc[1][nt][0], a11 = acc[1][nt][1], a12 = acc[1][nt][2], a13 = acc[1][nt][3];
            float s0 = a00 + a02 + a10 + a12;
            float s1 = a01 + a03 + a11 + a13;
            float q0 = a00 * a00 + a02 * a02 + a10 * a10 + a12 * a12;
            float q1 = a01 * a01 + a03 * a03 + a11 * a11 + a13 * a13;
            float mx0 = fmaxf(fmaxf(a00, a02), fmaxf(a10, a12));
            float mx1 = fmaxf(fmaxf(a01, a03), fmaxf(a11, a13));
            float mn0 = fminf(fminf(a00, a02), fminf(a10, a12));
            float mn1 = fminf(fminf(a01, a03), fminf(a11, a13));
            s0 = redg_sum(s0); s1 = redg_sum(s1);
            q0 = redg_sum(q0); q1 = redg_sum(q1);
            mx0 = redg_max(mx0); mx1 = redg_max(mx1);
            mn0 = redg_min(mn0); mn1 = redg_min(mn1);
            if (lane < 4) {
                int col = nw * 64 + nt * 8 + q2;
                *(float2*)(g_max2 + obase + col) = make_float2(mx0, mx1);
                *(float2*)(g_min2 + obase + col) = make_float2(mn0, mn1);
                redS[mw * 128 + col]     = s0;
                redS[mw * 128 + col + 1] = s1;
                redQ[mw * 128 + col]     = q0;
                redQ[mw * 128 + col + 1] = q1;
            }
        }
        __syncthreads();
        {
            int which = tid >> 7, c = tid & 127;
            const float* src = which ? redQ : redS;
            float s = src[c] + src[128 + c] + src[256 + c] + src[384 + c];
            g_part2[(size_t)which * NB2P * C2 + (size_t)(tile0 + t) * C2 + c] = s;
        }
    }
}

// ---------------------------------------------------------------------------
// Stats finalize
// ---------------------------------------------------------------------------
__global__ void stats_kernel(int layer, const float* __restrict__ gamma,
                             const float* __restrict__ beta) {
    const float* part; int nb, C; float* scale; float* shift;
    if (layer == 0)      { part = g_part0; nb = NB0T; C = C0;  scale = g_scale0; shift = g_shift0; }
    else if (layer == 1) { part = g_part1; nb = NB1P; C = C1O; scale = g_scale1; shift = g_shift1; }
    else                 { part = g_part2; nb = NB2P; C = C2;  scale = g_scale2; shift = g_shift2; }

    __shared__ float shs[256], shq[256];
    int c = blockIdx.x;
    int tid = threadIdx.x;
    float s = 0.0f, q = 0.0f;
    for (int i = tid; i < nb; i += 256) {
        s += part[(size_t)i * C + c];
        q += part[(size_t)(nb + i) * C + c];
    }
    shs[tid] = s; shq[tid] = q;
    __syncthreads();
    for (int off = 128; off > 0; off >>= 1) {
        if (tid < off) { shs[tid] += shs[tid + off]; shq[tid] += shq[tid + off]; }
        __syncthreads();
    }
    if (tid == 0) {
        float mean = shs[0] / CNT_;
        float var  = shq[0] / CNT_ - mean * mean;
        float sc   = gamma[c] * rsqrtf(var + EPS_);
        scale[c] = sc;
        shift[c] = beta[c] - mean * sc;
    }
}

// ---------------------------------------------------------------------------
// Final output
// ---------------------------------------------------------------------------
__global__ void final_kernel(float* __restrict__ out) {
    int o = blockIdx.x * 256 + threadIdx.x;
    if (o >= B_ * C2 * N2_) return;
    int n2 = o & (N2_ - 1);
    int c  = (o >> 10) & (C2 - 1);
    int b  = o >> 17;
    float sc = g_scale2[c], sh = g_shift2[c];
    size_t mi = (size_t)(b * N2_ + n2) * C2 + c;
    float v = (sc >= 0.0f) ? g_max2[mi] : g_min2[mi];
    out[o] = fmaxf(0.0f, fmaf(sc, v, sh));
}

// ---------------------------------------------------------------------------
// Launcher
// ---------------------------------------------------------------------------
extern "C" void kernel_launch(void* const* d_in, const int* in_sizes, int n_in,
                              void* d_out, int out_size) {
    const float* in_xyz     = (const float*)d_in[0];
    const float* out_xyz    = (const float*)d_in[1];
    const float* in_feature = (const float*)d_in[2];
    const int*   nbr        = (const int*)  d_in[3];
    const float* W0 = (const float*)d_in[4];
    const float* g0 = (const float*)d_in[5];
    const float* b0 = (const float*)d_in[6];
    const float* W1 = (const float*)d_in[7];
    const float* g1 = (const float*)d_in[8];
    const float* b1 = (const float*)d_in[9];
    const float* W2 = (const float*)d_in[10];
    const float* g2 = (const float*)d_in[11];
    const float* b2 = (const float*)d_in[12];
    float* out = (float*)d_out;

    cudaFuncSetAttribute(gemm0t_kernel, cudaFuncAttributeMaxDynamicSharedMemorySize, S0_SMEM);
    cudaFuncSetAttribute(gemm1t_kernel, cudaFuncAttributeMaxDynamicSharedMemorySize, T1_SMEM);
    cudaFuncSetAttribute(gemm2t_kernel, cudaFuncAttributeMaxDynamicSharedMemorySize, T2_SMEM);

    // launch order keeps gemm2t at index 5 for the fixed ncu -s 5 -c 1 window
    fused_pre_kernel<<<dim3(N1_ / 32 + 1, B_), dim3(32, 8)>>>(in_feature, in_xyz, out_xyz);

    gemm0t_kernel<<<NB0T, 256, S0_SMEM>>>(nbr, W0);
    stats_kernel<<<C0, 256>>>(0, g0, b0);

    gemm1t_kernel<<<NB1G, 256, T1_SMEM>>>(W1);
    stats_kernel<<<C1O, 256>>>(1, g1, b1);

    gemm2t_kernel<<<NB2G, 256, T2_SMEM>>>(W2);
    stats_kernel<<<C2, 256>>>(2, g2, b2);

    final_kernel<<<(B_ * C2 * N2_ + 255) / 256, 256>>>(out);
}